// round 8
// baseline (speedup 1.0000x reference)
#include <cuda_runtime.h>
#include <math.h>
#include <stdint.h>

#define N_TOK 1024
#define DIMV  512
#define HEADS 8
#define DH    64
#define JPAD  1088          // 17*64 = 34*32
#define INV_EPS 10.0f
#define EPSF    0.1f
#define LOGK    2.0794415416798357f
#define CD_ITERS 50

// ---------------- scratch (hi/lo tf32 split planes stored as f32) ----------------
__device__ float g_xnh[N_TOK * DIMV], g_xnl[N_TOK * DIMV];
__device__ float g_wh [512 * 1536],   g_wl [512 * 1536];
__device__ float g_woh[512 * 512],    g_wol[512 * 512];
__device__ float g_qh [HEADS * N_TOK * DH], g_ql[HEADS * N_TOK * DH];
__device__ float g_kh [HEADS * JPAD * DH],  g_kl[HEADS * JPAD * DH];
__device__ float g_vh [HEADS * JPAD * DH],  g_vl[HEADS * JPAD * DH];
__device__ float g_s  [HEADS * N_TOK * JPAD];
__device__ float g_o  [N_TOK * DIMV], g_o2[N_TOK * DIMV];

// ---------------- tf32 helpers ----------------
__device__ __forceinline__ float tf32_rna(float x) {
    uint32_t r; asm("cvt.rna.tf32.f32 %0, %1;" : "=r"(r) : "f"(x));
    return __uint_as_float(r);
}
__device__ __forceinline__ void split_tf(float x, float& hi, float& lo) {
    hi = tf32_rna(x);
    lo = tf32_rna(x - hi);
}
// D(16x8,f32) += A(16x8,tf32 row) * B(8x8,tf32 col)
__device__ __forceinline__ void mma8(float* d, const float* a, const float* b) {
    asm volatile(
        "mma.sync.aligned.m16n8k8.row.col.f32.tf32.tf32.f32 "
        "{%0,%1,%2,%3}, {%4,%5,%6,%7}, {%8,%9}, {%0,%1,%2,%3};"
        : "+f"(d[0]), "+f"(d[1]), "+f"(d[2]), "+f"(d[3])
        : "r"(__float_as_uint(a[0])), "r"(__float_as_uint(a[1])),
          "r"(__float_as_uint(a[2])), "r"(__float_as_uint(a[3])),
          "r"(__float_as_uint(b[0])), "r"(__float_as_uint(b[1])));
}

// ---------------- block reduction ----------------
__device__ __forceinline__ float block_sum_256(float v, float* red) {
#pragma unroll
    for (int o = 16; o; o >>= 1) v += __shfl_xor_sync(0xffffffffu, v, o);
    __syncthreads();
    if ((threadIdx.x & 31) == 0) red[threadIdx.x >> 5] = v;
    __syncthreads();
    v = red[threadIdx.x & 7];
#pragma unroll
    for (int o = 4; o; o >>= 1) v += __shfl_xor_sync(0xffffffffu, v, o);
    return v;
}

// ---------------- fused LayerNorm (split planes out) + null-kv/pad fill ----------------
__global__ void ln_fill_kernel(const float* __restrict__ x, const float* __restrict__ gam,
                               const float* __restrict__ bet,
                               const float* __restrict__ null_kv) {
    if (blockIdx.x >= 1024) {
        const int idx = (blockIdx.x - 1024) * 256 + threadIdx.x;
        const int h = idx >> 12;
        const int r = (idx >> 6) & 63;
        const int d = idx & 63;
        if (r < 2) {
            float kv = null_kv[((0 * HEADS + h) * 2 + r) * DH + d];
            float vv = null_kv[((1 * HEADS + h) * 2 + r) * DH + d];
            float hi, lo;
            split_tf(kv, hi, lo);
            g_kh[(h * JPAD + r) * DH + d] = hi; g_kl[(h * JPAD + r) * DH + d] = lo;
            split_tf(vv, hi, lo);
            g_vh[(h * JPAD + r) * DH + d] = hi; g_vl[(h * JPAD + r) * DH + d] = lo;
        } else {
            const int j = 1024 + r;     // 1026..1087
            g_kh[(h * JPAD + j) * DH + d] = 0.0f; g_kl[(h * JPAD + j) * DH + d] = 0.0f;
            g_vh[(h * JPAD + j) * DH + d] = 0.0f; g_vl[(h * JPAD + j) * DH + d] = 0.0f;
        }
        return;
    }
    __shared__ float red[8];
    const int row = blockIdx.x;
    const int tid = threadIdx.x;
    const float v0 = x[row * DIMV + tid];
    const float v1 = x[row * DIMV + tid + 256];
    float s  = v0 + v1;
    float sq = v0 * v0 + v1 * v1;
    s  = block_sum_256(s,  red);
    sq = block_sum_256(sq, red);
    const float mean = s * (1.0f / 512.0f);
    const float var  = sq * (1.0f / 512.0f) - mean * mean;
    const float rstd = rsqrtf(var + 1e-5f);
    const float y0 = (v0 - mean) * rstd * gam[tid]       + bet[tid];
    const float y1 = (v1 - mean) * rstd * gam[tid + 256] + bet[tid + 256];
    float hi, lo;
    split_tf(y0, hi, lo);
    g_xnh[row * DIMV + tid] = hi; g_xnl[row * DIMV + tid] = lo;
    split_tf(y1, hi, lo);
    g_xnh[row * DIMV + tid + 256] = hi; g_xnl[row * DIMV + tid + 256] = lo;
}

// ---------------- split both weight matrices ----------------
__global__ void wsplit_kernel(const float* __restrict__ Wqkv, const float* __restrict__ Wout) {
    const int g4 = (blockIdx.x * 256 + threadIdx.x) * 4;
    float hi, lo;
    if (g4 < 512 * 1536) {
        float4 v = *(const float4*)(Wqkv + g4);
        split_tf(v.x, hi, lo); g_wh[g4 + 0] = hi; g_wl[g4 + 0] = lo;
        split_tf(v.y, hi, lo); g_wh[g4 + 1] = hi; g_wl[g4 + 1] = lo;
        split_tf(v.z, hi, lo); g_wh[g4 + 2] = hi; g_wl[g4 + 2] = lo;
        split_tf(v.w, hi, lo); g_wh[g4 + 3] = hi; g_wl[g4 + 3] = lo;
    } else {
        const int o = g4 - 512 * 1536;
        float4 v = *(const float4*)(Wout + o);
        split_tf(v.x, hi, lo); g_woh[o + 0] = hi; g_wol[o + 0] = lo;
        split_tf(v.y, hi, lo); g_woh[o + 1] = hi; g_wol[o + 1] = lo;
        split_tf(v.z, hi, lo); g_woh[o + 2] = hi; g_wol[o + 2] = lo;
        split_tf(v.w, hi, lo); g_woh[o + 3] = hi; g_wol[o + 3] = lo;
    }
}

// ---------------- QKV GEMM (tf32 mma): block 128x64, warp 32x32 ----------------
__global__ void __launch_bounds__(256) gemm_qkv() {
    __shared__ float Ah[16][132], Al[16][132], Bh[16][68], Bl[16][68];
    const int bx = blockIdx.x, by = blockIdx.y, tid = threadIdx.x;
    const int wid = tid >> 5, lane = tid & 31;
    const int wm = wid & 3, wn = wid >> 2;
    const int grp = lane >> 2, lq = lane & 3;
    const int arow = tid >> 2, akseg = (tid & 3) << 2;
    const int bkrow = tid >> 4, bnseg = (tid & 15) << 2;
    float acc[2][4][4] = {};

    for (int k0 = 0; k0 < 512; k0 += 16) {
        float4 ah0 = *(const float4*)(g_xnh + (by * 128 + arow) * 512 + k0 + akseg);
        float4 ah1 = *(const float4*)(g_xnh + (by * 128 + arow + 64) * 512 + k0 + akseg);
        float4 al0 = *(const float4*)(g_xnl + (by * 128 + arow) * 512 + k0 + akseg);
        float4 al1 = *(const float4*)(g_xnl + (by * 128 + arow + 64) * 512 + k0 + akseg);
        float4 bh4 = *(const float4*)(g_wh + (size_t)(k0 + bkrow) * 1536 + bx * 64 + bnseg);
        float4 bl4 = *(const float4*)(g_wl + (size_t)(k0 + bkrow) * 1536 + bx * 64 + bnseg);
        __syncthreads();
        Ah[akseg + 0][arow] = ah0.x; Ah[akseg + 1][arow] = ah0.y;
        Ah[akseg + 2][arow] = ah0.z; Ah[akseg + 3][arow] = ah0.w;
        Ah[akseg + 0][arow + 64] = ah1.x; Ah[akseg + 1][arow + 64] = ah1.y;
        Ah[akseg + 2][arow + 64] = ah1.z; Ah[akseg + 3][arow + 64] = ah1.w;
        Al[akseg + 0][arow] = al0.x; Al[akseg + 1][arow] = al0.y;
        Al[akseg + 2][arow] = al0.z; Al[akseg + 3][arow] = al0.w;
        Al[akseg + 0][arow + 64] = al1.x; Al[akseg + 1][arow + 64] = al1.y;
        Al[akseg + 2][arow + 64] = al1.z; Al[akseg + 3][arow + 64] = al1.w;
        *(float4*)&Bh[bkrow][bnseg] = bh4;
        *(float4*)&Bl[bkrow][bnseg] = bl4;
        __syncthreads();
#pragma unroll
        for (int ks = 0; ks < 2; ks++) {
            const int kb = ks * 8;
            float a_h[2][4], a_l[2][4], b_h[4][2], b_l[4][2];
#pragma unroll
            for (int mt = 0; mt < 2; mt++) {
                const int mb = wm * 32 + mt * 16;
                a_h[mt][0] = Ah[kb + lq][mb + grp];     a_h[mt][1] = Ah[kb + lq][mb + grp + 8];
                a_h[mt][2] = Ah[kb + lq + 4][mb + grp]; a_h[mt][3] = Ah[kb + lq + 4][mb + grp + 8];
                a_l[mt][0] = Al[kb + lq][mb + grp];     a_l[mt][1] = Al[kb + lq][mb + grp + 8];
                a_l[mt][2] = Al[kb + lq + 4][mb + grp]; a_l[mt][3] = Al[kb + lq + 4][mb + grp + 8];
            }
#pragma unroll
            for (int nt = 0; nt < 4; nt++) {
                const int nb = wn * 32 + nt * 8;
                b_h[nt][0] = Bh[kb + lq][nb + grp]; b_h[nt][1] = Bh[kb + lq + 4][nb + grp];
                b_l[nt][0] = Bl[kb + lq][nb + grp]; b_l[nt][1] = Bl[kb + lq + 4][nb + grp];
            }
#pragma unroll
            for (int mt = 0; mt < 2; mt++)
#pragma unroll
                for (int nt = 0; nt < 4; nt++) {
                    mma8(acc[mt][nt], a_h[mt], b_l[nt]);
                    mma8(acc[mt][nt], a_l[mt], b_h[nt]);
                    mma8(acc[mt][nt], a_h[mt], b_h[nt]);
                }
        }
    }
#pragma unroll
    for (int mt = 0; mt < 2; mt++)
#pragma unroll
        for (int nt = 0; nt < 4; nt++)
#pragma unroll
            for (int c = 0; c < 4; c++) {
                const int row = by * 128 + wm * 32 + mt * 16 + grp + ((c >> 1) << 3);
                const int col = bx * 64 + wn * 32 + nt * 8 + 2 * lq + (c & 1);
                float val = acc[mt][nt][c];
                const int w = col >> 9, h = (col >> 6) & 7, d = col & 63;
                float hi, lo;
                if (w == 0) {
                    split_tf(val * 0.125f, hi, lo);
                    g_qh[(h * N_TOK + row) * DH + d] = hi;
                    g_ql[(h * N_TOK + row) * DH + d] = lo;
                } else if (w == 1) {
                    split_tf(val, hi, lo);
                    g_kh[(h * JPAD + row + 2) * DH + d] = hi;
                    g_kl[(h * JPAD + row + 2) * DH + d] = lo;
                } else {
                    split_tf(val, hi, lo);
                    g_vh[(h * JPAD + row + 2) * DH + d] = hi;
                    g_vl[(h * JPAD + row + 2) * DH + d] = lo;
                }
            }
}

// ---------------- sim = q.k^T (tf32 mma): 128x64 causal tiles, warp 32x32 -------------
__global__ void __launch_bounds__(256) sim_kernel() {
    const int f = blockIdx.x;
    const int h = blockIdx.y;
    int it2 = __float2int_rd(sqrtf((float)(f + 1))) - 1;
    while ((it2 + 1) * (it2 + 3) <= f) it2++;
    while (it2 * (it2 + 2) > f) it2--;
    const int jt = f - it2 * (it2 + 2);

    __shared__ float Qh[16][132], Ql[16][132], Kh[16][68], Kl[16][68];
    const int tid = threadIdx.x;
    const int wid = tid >> 5, lane = tid & 31;
    const int wm = wid & 3, wn = wid >> 2;
    const int grp = lane >> 2, lq = lane & 3;
    const int qrow = tid >> 1, qseg = (tid & 1) << 3;
    const int krow = tid >> 2, kseg = (tid & 3) << 2;
    float acc[2][4][4] = {};

#pragma unroll
    for (int dc = 0; dc < 64; dc += 16) {
        const int qbase = ((h << 10) + it2 * 128 + qrow) * DH + dc + qseg;
        float4 q0 = *(const float4*)(g_qh + qbase);
        float4 q1 = *(const float4*)(g_qh + qbase + 4);
        float4 q2 = *(const float4*)(g_ql + qbase);
        float4 q3 = *(const float4*)(g_ql + qbase + 4);
        const int kbase = (h * JPAD + jt * 64 + krow) * DH + dc + kseg;
        float4 kh4 = *(const float4*)(g_kh + kbase);
        float4 kl4 = *(const float4*)(g_kl + kbase);
        __syncthreads();
        Qh[qseg + 0][qrow] = q0.x; Qh[qseg + 1][qrow] = q0.y;
        Qh[qseg + 2][qrow] = q0.z; Qh[qseg + 3][qrow] = q0.w;
        Qh[qseg + 4][qrow] = q1.x; Qh[qseg + 5][qrow] = q1.y;
        Qh[qseg + 6][qrow] = q1.z; Qh[qseg + 7][qrow] = q1.w;
        Ql[qseg + 0][qrow] = q2.x; Ql[qseg + 1][qrow] = q2.y;
        Ql[qseg + 2][qrow] = q2.z; Ql[qseg + 3][qrow] = q2.w;
        Ql[qseg + 4][qrow] = q3.x; Ql[qseg + 5][qrow] = q3.y;
        Ql[qseg + 6][qrow] = q3.z; Ql[qseg + 7][qrow] = q3.w;
        Kh[kseg + 0][krow] = kh4.x; Kh[kseg + 1][krow] = kh4.y;
        Kh[kseg + 2][krow] = kh4.z; Kh[kseg + 3][krow] = kh4.w;
        Kl[kseg + 0][krow] = kl4.x; Kl[kseg + 1][krow] = kl4.y;
        Kl[kseg + 2][krow] = kl4.z; Kl[kseg + 3][krow] = kl4.w;
        __syncthreads();
#pragma unroll
        for (int ks = 0; ks < 2; ks++) {
            const int kb = ks * 8;
            float a_h[2][4], a_l[2][4], b_h[4][2], b_l[4][2];
#pragma unroll
            for (int mt = 0; mt < 2; mt++) {
                const int mb = wm * 32 + mt * 16;
                a_h[mt][0] = Qh[kb + lq][mb + grp];     a_h[mt][1] = Qh[kb + lq][mb + grp + 8];
                a_h[mt][2] = Qh[kb + lq + 4][mb + grp]; a_h[mt][3] = Qh[kb + lq + 4][mb + grp + 8];
                a_l[mt][0] = Ql[kb + lq][mb + grp];     a_l[mt][1] = Ql[kb + lq][mb + grp + 8];
                a_l[mt][2] = Ql[kb + lq + 4][mb + grp]; a_l[mt][3] = Ql[kb + lq + 4][mb + grp + 8];
            }
#pragma unroll
            for (int nt = 0; nt < 4; nt++) {
                const int nb = wn * 32 + nt * 8;
                b_h[nt][0] = Kh[kb + lq][nb + grp]; b_h[nt][1] = Kh[kb + lq + 4][nb + grp];
                b_l[nt][0] = Kl[kb + lq][nb + grp]; b_l[nt][1] = Kl[kb + lq + 4][nb + grp];
            }
#pragma unroll
            for (int mt = 0; mt < 2; mt++)
#pragma unroll
                for (int nt = 0; nt < 4; nt++) {
                    mma8(acc[mt][nt], a_h[mt], b_l[nt]);
                    mma8(acc[mt][nt], a_l[mt], b_h[nt]);
                    mma8(acc[mt][nt], a_h[mt], b_h[nt]);
                }
        }
    }
#pragma unroll
    for (int mt = 0; mt < 2; mt++)
#pragma unroll
        for (int nt = 0; nt < 4; nt++) {
            const int i0 = it2 * 128 + wm * 32 + mt * 16 + grp;
            const int j0 = jt * 64 + wn * 32 + nt * 8 + 2 * lq;
            float* s0 = g_s + (size_t)(h * N_TOK + i0) * JPAD + j0;
            *(float2*)s0 = make_float2(acc[mt][nt][0], acc[mt][nt][1]);
            float* s1 = g_s + (size_t)(h * N_TOK + i0 + 8) * JPAD + j0;
            *(float2*)s1 = make_float2(acc[mt][nt][2], acc[mt][nt][3]);
        }
}

// ---------------- coordinate descent (unchanged) ----------------
template<int MAXU>
__device__ __forceinline__ void cd_row(float* __restrict__ srow, int lane, int jmax,
                                       int nchunk, int chunks) {
    float E1[MAXU];
    float tm = -3.4e38f;
#pragma unroll
    for (int u = 0; u < MAXU; u++) {
        E1[u] = -3.4e38f;
        if (u < nchunk) {
            const int j = lane + u * 32;
            if (j < jmax) { E1[u] = srow[j]; tm = fmaxf(tm, E1[u]); }
        }
    }
#pragma unroll
    for (int o = 16; o; o >>= 1) tm = fmaxf(tm, __shfl_xor_sync(0xffffffffu, tm, o));
    const float m = tm;
#pragma unroll
    for (int u = 0; u < MAXU; u++)
        if (u < nchunk)
            E1[u] = (E1[u] > -3.0e38f) ? __expf((E1[u] - m) * INV_EPS) : 0.0f;

    float a = EPSF * (LOGK - __logf((float)jmax));

    for (int it = 1; it < CD_ITERS; it++) {
        const float w = __expf((a + m) * INV_EPS);
        float ls0 = 0.0f, ls1 = 0.0f;
#pragma unroll
        for (int u = 0; u < MAXU; u++) {
            if (u < nchunk) {
                const float e = E1[u];
                const float c = fminf(e, w * (e * e));
                if (u & 1) ls1 += c; else ls0 += c;
            }
        }
        float ls = ls0 + ls1;
#pragma unroll
        for (int o = 16; o; o >>= 1) ls += __shfl_xor_sync(0xffffffffu, ls, o);
        const float a_new = EPSF * LOGK - m - EPSF * __logf(ls);
        const float da = fabsf(a_new - a);
        a = a_new;
        if (da < 5e-7f) break;
    }

    const float w = __expf((a + m) * INV_EPS);
#pragma unroll
    for (int u = 0; u < MAXU + 3; u++) {
        if (u < chunks) {
            const int j = lane + u * 32;
            float val = 0.0f;
            if (u < MAXU && u < nchunk) {
                const float eu = w * E1[u];
                val = fminf(eu, eu * eu);
            }
            srow[j] = val;
        }
    }
}

__global__ void cd_kernel() {
    const int wg   = (blockIdx.x * blockDim.x + threadIdx.x) >> 5;
    const int lane = threadIdx.x & 31;
    const int i = wg >> 3, h = wg & 7;
    const int jmax = i + 3;
    const int nchunk = (jmax + 31) >> 5;
    const int chunks = ((i >> 6) + 2) << 1;
    float* srow = g_s + (size_t)(h * N_TOK + i) * JPAD;
    if (i < 254)      cd_row<8 >(srow, lane, jmax, nchunk, chunks);
    else if (i < 510) cd_row<16>(srow, lane, jmax, nchunk, chunks);
    else if (i < 766) cd_row<24>(srow, lane, jmax, nchunk, chunks);
    else              cd_row<33>(srow, lane, jmax, nchunk, chunks);
}

// ---------------- av = attn.v (tf32 mma): block 64x64, warp 32x16, split-K ------------
__global__ void __launch_bounds__(256) av_kernel() {
    const int it = blockIdx.x;
    const int h  = blockIdx.y;
    const int sp = blockIdx.z;
    const int T = it + 2;                 // 64-tiles of j
    const int half = T >> 1;
    const int jc0 = (sp ? half : 0) * 2;  // 32-chunks
    const int jc1 = (sp ? T : half) * 2;

    __shared__ float Ph[32][68], Pl[32][68], Vh[32][68], Vl[32][68];
    const int tid = threadIdx.x;
    const int wid = tid >> 5, lane = tid & 31;
    const int wm = wid & 1, wn = wid >> 1;
    const int grp = lane >> 2, lq = lane & 3;
    const int prow = tid >> 2, pseg = (tid & 3) << 3;
    const int vrow = tid >> 3, vseg = (tid & 7) << 3;
    float acc[2][2][4] = {};

    for (int jc = jc0; jc < jc1; jc++) {
        const size_t pbase = (size_t)(h * N_TOK + it * 64 + prow) * JPAD + jc * 32 + pseg;
        float4 p0 = *(const float4*)(g_s + pbase);
        float4 p1 = *(const float4*)(g_s + pbase + 4);
        const int vbase = (h * JPAD + jc * 32 + vrow) * DH + vseg;
        float4 vh0 = *(const float4*)(g_vh + vbase);
        float4 vh1 = *(const float4*)(g_vh + vbase + 4);
        float4 vl0 = *(const float4*)(g_vl + vbase);
        float4 vl1 = *(const float4*)(g_vl + vbase + 4);
        __syncthreads();
        {
            float hi, lo;
            split_tf(p0.x, hi, lo); Ph[pseg + 0][prow] = hi; Pl[pseg + 0][prow] = lo;
            split_tf(p0.y, hi, lo); Ph[pseg + 1][prow] = hi; Pl[pseg + 1][prow] = lo;
            split_tf(p0.z, hi, lo); Ph[pseg + 2][prow] = hi; Pl[pseg + 2][prow] = lo;
            split_tf(p0.w, hi, lo); Ph[pseg + 3][prow] = hi; Pl[pseg + 3][prow] = lo;
            split_tf(p1.x, hi, lo); Ph[pseg + 4][prow] = hi; Pl[pseg + 4][prow] = lo;
            split_tf(p1.y, hi, lo); Ph[pseg + 5][prow] = hi; Pl[pseg + 5][prow] = lo;
            split_tf(p1.z, hi, lo); Ph[pseg + 6][prow] = hi; Pl[pseg + 6][prow] = lo;
            split_tf(p1.w, hi, lo); Ph[pseg + 7][prow] = hi; Pl[pseg + 7][prow] = lo;
        }
        *(float4*)&Vh[vrow][vseg]     = vh0;
        *(float4*)&Vh[vrow][vseg + 4] = vh1;
        *(float4*)&Vl[vrow][vseg]     = vl0;
        *(float4*)&Vl[vrow][vseg + 4] = vl1;
        __syncthreads();
#pragma unroll
        for (int ks = 0; ks < 4; ks++) {
            const int kb = ks * 8;
            float a_h[2][4], a_l[2][4], b_h[2][2], b_l[2][2];
#pragma unroll
            for (int mt = 0; mt < 2; mt++) {
                const int mb = wm * 32 + mt * 16;
                a_h[mt][0] = Ph[kb + lq][mb + grp];     a_h[mt][1] = Ph[kb + lq][mb + grp + 8];
                a_h[mt][2] = Ph[kb + lq + 4][mb + grp]; a_h[mt][3] = Ph[kb + lq + 4][mb + grp + 8];
                a_l[mt][0] = Pl[kb + lq][mb + grp];     a_l[mt][1] = Pl[kb + lq][mb + grp + 8];
                a_l[mt][2] = Pl[kb + lq + 4][mb + grp]; a_l[mt][3] = Pl[kb + lq + 4][mb + grp + 8];
            }
#pragma unroll
            for (int nt = 0; nt < 2; nt++) {
                const int nb = wn * 16 + nt * 8;
                b_h[nt][0] = Vh[kb + lq][nb + grp]; b_h[nt][1] = Vh[kb + lq + 4][nb + grp];
                b_l[nt][0] = Vl[kb + lq][nb + grp]; b_l[nt][1] = Vl[kb + lq + 4][nb + grp];
            }
#pragma unroll
            for (int mt = 0; mt < 2; mt++)
#pragma unroll
                for (int nt = 0; nt < 2; nt++) {
                    mma8(acc[mt][nt], a_h[mt], b_l[nt]);
                    mma8(acc[mt][nt], a_l[mt], b_h[nt]);
                    mma8(acc[mt][nt], a_h[mt], b_h[nt]);
                }
        }
    }
    float* outp = sp ? g_o2 : g_o;
#pragma unroll
    for (int mt = 0; mt < 2; mt++)
#pragma unroll
        for (int nt = 0; nt < 2; nt++) {
            const int row = it * 64 + wm * 32 + mt * 16 + grp;
            const int d = wn * 16 + nt * 8 + 2 * lq;
            *(float2*)(outp + row * DIMV + h * DH + d) =
                make_float2(acc[mt][nt][0], acc[mt][nt][1]);
            *(float2*)(outp + (row + 8) * DIMV + h * DH + d) =
                make_float2(acc[mt][nt][2], acc[mt][nt][3]);
        }
}

// ---------------- out projection (tf32 mma): block 64x64, warp 32x16 ------------------
__global__ void __launch_bounds__(256) gemm_proj(float* __restrict__ C) {
    __shared__ float Ah[16][68], Al[16][68], Bh[16][68], Bl[16][68];
    const int bx = blockIdx.x, by = blockIdx.y, tid = threadIdx.x;
    const int wid = tid >> 5, lane = tid & 31;
    const int wm = wid & 1, wn = wid >> 1;
    const int grp = lane >> 2, lq = lane & 3;
    const int arow = tid >> 2, akseg = (tid & 3) << 2;
    const int bkrow = tid >> 4, bnseg = (tid & 15) << 2;
    float acc[2][2][4] = {};

    for (int k0 = 0; k0 < 512; k0 += 16) {
        const int abase = (by * 64 + arow) * 512 + k0 + akseg;
        float4 o1 = *(const float4*)(g_o + abase);
        float4 o2 = *(const float4*)(g_o2 + abase);
        o1.x += o2.x; o1.y += o2.y; o1.z += o2.z; o1.w += o2.w;
        float4 bh4 = *(const float4*)(g_woh + (size_t)(k0 + bkrow) * 512 + bx * 64 + bnseg);
        float4 bl4 = *(const float4*)(g_wol + (size_t)(k0 + bkrow) * 512 + bx * 64 + bnseg);
        __syncthreads();
        {
            float hi, lo;
            split_tf(o1.x, hi, lo); Ah[akseg + 0][arow] = hi; Al[akseg + 0][arow] = lo;
            split_tf(o1.y, hi, lo); Ah[akseg + 1][arow] = hi; Al[akseg + 1][arow] = lo;
            split_tf(o1.z, hi, lo); Ah[akseg + 2][arow] = hi; Al[akseg + 2][arow] = lo;
            split_tf(o1.w, hi, lo); Ah[akseg + 3][arow] = hi; Al[akseg + 3][arow] = lo;
        }
        *(float4*)&Bh[bkrow][bnseg] = bh4;
        *(float4*)&Bl[bkrow][bnseg] = bl4;
        __syncthreads();
#pragma unroll
        for (int ks = 0; ks < 2; ks++) {
            const int kb = ks * 8;
            float a_h[2][4], a_l[2][4], b_h[2][2], b_l[2][2];
#pragma unroll
            for (int mt = 0; mt < 2; mt++) {
                const int mb = wm * 32 + mt * 16;
                a_h[mt][0] = Ah[kb + lq][mb + grp];     a_h[mt][1] = Ah[kb + lq][mb + grp + 8];
                a_h[mt][2] = Ah[kb + lq + 4][mb + grp]; a_h[mt][3] = Ah[kb + lq + 4][mb + grp + 8];
                a_l[mt][0] = Al[kb + lq][mb + grp];     a_l[mt][1] = Al[kb + lq][mb + grp + 8];
                a_l[mt][2] = Al[kb + lq + 4][mb + grp]; a_l[mt][3] = Al[kb + lq + 4][mb + grp + 8];
            }
#pragma unroll
            for (int nt = 0; nt < 2; nt++) {
                const int nb = wn * 16 + nt * 8;
                b_h[nt][0] = Bh[kb + lq][nb + grp]; b_h[nt][1] = Bh[kb + lq + 4][nb + grp];
                b_l[nt][0] = Bl[kb + lq][nb + grp]; b_l[nt][1] = Bl[kb + lq + 4][nb + grp];
            }
#pragma unroll
            for (int mt = 0; mt < 2; mt++)
#pragma unroll
                for (int nt = 0; nt < 2; nt++) {
                    mma8(acc[mt][nt], a_h[mt], b_l[nt]);
                    mma8(acc[mt][nt], a_l[mt], b_h[nt]);
                    mma8(acc[mt][nt], a_h[mt], b_h[nt]);
                }
        }
    }
#pragma unroll
    for (int mt = 0; mt < 2; mt++)
#pragma unroll
        for (int nt = 0; nt < 2; nt++) {
            const int row = by * 64 + wm * 32 + mt * 16 + grp;
            const int col = bx * 64 + wn * 16 + nt * 8 + 2 * lq;
            *(float2*)(C + row * 512 + col) = make_float2(acc[mt][nt][0], acc[mt][nt][1]);
            *(float2*)(C + (row + 8) * 512 + col) = make_float2(acc[mt][nt][2], acc[mt][nt][3]);
        }
}

// ---------------- launch ----------------
extern "C" void kernel_launch(void* const* d_in, const int* in_sizes, int n_in,
                              void* d_out, int out_size) {
    const float* x       = (const float*)d_in[0];
    const float* w_qkv   = (const float*)d_in[1];
    const float* w_out   = (const float*)d_in[2];
    const float* null_kv = (const float*)d_in[3];
    const float* ln_g    = (const float*)d_in[4];
    const float* ln_b    = (const float*)d_in[5];
    float* out = (float*)d_out;

    ln_fill_kernel<<<1152, 256>>>(x, ln_g, ln_b, null_kv);
    wsplit_kernel <<<1024, 256>>>(w_qkv, w_out);
    gemm_qkv      <<<dim3(24, 8), 256>>>();
    sim_kernel    <<<dim3(80, HEADS), 256>>>();
    cd_kernel     <<<2048, 128>>>();
    av_kernel     <<<dim3(16, HEADS, 2), 256>>>();
    gemm_proj     <<<dim3(8, 16), 256>>>(out);
}